// round 1
// baseline (speedup 1.0000x reference)
#include <cuda_runtime.h>
#include <cuda_bf16.h>

#define BB   32
#define CC   128
#define HH   56
#define WW   56
#define OUTC 256
#define KK   4
#define HIDN 64
#define HW   (HH*WW)

// conv tiling
#define OT    64      // o-channels per CTA
#define RT    4       // output rows per CTA
#define CSTEP 4       // input channels per smem stage

// scratch (device globals: allocation-free rule)
__device__ float g_pooled[BB*CC];
__device__ float g_attn[BB*KK];
__device__ float g_weight[(size_t)BB*CC*9*OUTC];   // layout [b][c][ij][o], 37.7 MB

// ---------------------------------------------------------------- pool
__global__ void pool_kernel(const float* __restrict__ x) {
    int bc = blockIdx.x;                       // b*CC + c
    const float4* p = (const float4*)(x + (size_t)bc * HW);
    float s = 0.f;
    for (int i = threadIdx.x; i < HW/4; i += blockDim.x) {
        float4 v = p[i];
        s += v.x + v.y + v.z + v.w;
    }
    #pragma unroll
    for (int o = 16; o; o >>= 1) s += __shfl_down_sync(0xffffffff, s, o);
    __shared__ float ws[8];
    int lane = threadIdx.x & 31, wid = threadIdx.x >> 5;
    if (lane == 0) ws[wid] = s;
    __syncthreads();
    if (threadIdx.x == 0) {
        float t = 0.f;
        #pragma unroll
        for (int i = 0; i < 8; i++) t += ws[i];
        g_pooled[bc] = t * (1.0f / (float)HW);
    }
}

// ---------------------------------------------------------------- attn (fc1+relu+fc2+softmax)
__global__ void attn_kernel(const float* __restrict__ fc1_w, const float* __restrict__ fc1_b,
                            const float* __restrict__ fc2_w, const float* __restrict__ fc2_b) {
    int b = blockIdx.x;
    __shared__ float sp[CC];
    __shared__ float hdn[HIDN];
    int t = threadIdx.x;                       // 0..63
    for (int i = t; i < CC; i += HIDN) sp[i] = g_pooled[b*CC + i];
    __syncthreads();
    float a = fc1_b[t];
    #pragma unroll 8
    for (int c = 0; c < CC; c++) a += sp[c] * fc1_w[t*CC + c];
    hdn[t] = fmaxf(a, 0.f);
    __syncthreads();
    if (t == 0) {
        float lg[KK];
        float mx = -1e30f;
        #pragma unroll
        for (int k = 0; k < KK; k++) {
            float s = fc2_b[k];
            for (int h = 0; h < HIDN; h++) s += hdn[h] * fc2_w[k*HIDN + h];
            lg[k] = s; mx = fmaxf(mx, s);
        }
        float den = 0.f;
        #pragma unroll
        for (int k = 0; k < KK; k++) { lg[k] = expf(lg[k] - mx); den += lg[k]; }
        float inv = 1.0f / den;
        #pragma unroll
        for (int k = 0; k < KK; k++) g_attn[b*KK + k] = lg[k] * inv;
    }
}

// ---------------------------------------------------------------- weight synthesis
// g_weight[b][c][ij][o] = sum_k attn[b][k] * bank[k][o][c][ij]
__global__ void synth_kernel(const float* __restrict__ bank) {
    __shared__ float sat[BB*KK];
    if (threadIdx.x < BB*KK) sat[threadIdx.x] = g_attn[threadIdx.x];
    __syncthreads();
    int pos = blockIdx.x * blockDim.x + threadIdx.x;   // < CC*9*OUTC = 294912
    int o   = pos & (OUTC-1);
    int cij = pos >> 8;                                // c*9+ij
    float bv[KK];
    #pragma unroll
    for (int k = 0; k < KK; k++)
        bv[k] = bank[((size_t)k*OUTC + o) * (CC*9) + cij];
    #pragma unroll 4
    for (int b = 0; b < BB; b++) {
        float w = 0.f;
        #pragma unroll
        for (int k = 0; k < KK; k++) w += sat[b*KK + k] * bv[k];
        g_weight[(size_t)b * (CC*9*OUTC) + pos] = w;
    }
}

// ---------------------------------------------------------------- direct conv
// CTA: one batch b, OT=64 o-channels, RT=4 output rows (full width 56).
// Thread: warp id = o-group (8 o's), lane = position group (7 positions strided by 32).
__global__ __launch_bounds__(256, 2) void conv_kernel(const float* __restrict__ x,
                                                      float* __restrict__ out) {
    __shared__ float sin_[CSTEP*(RT+2)*(WW+2)];   // 4*6*58 = 1392 floats
    __shared__ float sw  [CSTEP*9*OT];            // [cc][ij][o] = 2304 floats

    int rt = blockIdx.x;            // 0..13
    int ot = blockIdx.y;            // 0..3
    int b  = blockIdx.z;            // 0..31
    int row0  = rt * RT;
    int obase = ot * OT;
    int t  = threadIdx.x;
    int og = t >> 5;                // warp id 0..7  (uniform per warp)
    int pg = t & 31;

    int rowl[7], coll[7], soff[7];
    #pragma unroll
    for (int m = 0; m < 7; m++) {
        int pos = pg + 32*m;        // 0..223
        rowl[m] = pos / WW;
        coll[m] = pos % WW;
        soff[m] = rowl[m]*(WW+2) + coll[m];
    }

    float acc[8][7];
    #pragma unroll
    for (int oo = 0; oo < 8; oo++)
        #pragma unroll
        for (int m = 0; m < 7; m++) acc[oo][m] = 0.f;

    const float* wg = g_weight + (size_t)b * (CC*9*OUTC);

    for (int c0 = 0; c0 < CC; c0 += CSTEP) {
        __syncthreads();
        // input patch with halo (zero padded), coalesced over columns
        for (int idx = t; idx < CSTEP*(RT+2)*(WW+2); idx += 256) {
            int cc  = idx / ((RT+2)*(WW+2));
            int rem = idx % ((RT+2)*(WW+2));
            int rr  = rem / (WW+2);
            int cl  = rem % (WW+2);
            int gr  = row0 - 1 + rr;
            int gc  = cl - 1;
            float v = 0.f;
            if (gr >= 0 && gr < HH && gc >= 0 && gc < WW)
                v = x[(((size_t)b*CC + c0 + cc)*HH + gr)*WW + gc];
            sin_[idx] = v;
        }
        // weights, coalesced over o (64-float contiguous runs)
        for (int idx = t; idx < CSTEP*9*OT; idx += 256) {
            int o   = idx & 63;
            int cij = idx >> 6;     // cc*9+ij
            sw[idx] = wg[((size_t)c0*9 + cij)*OUTC + obase + o];
        }
        __syncthreads();

        #pragma unroll
        for (int cc = 0; cc < CSTEP; cc++) {
            #pragma unroll
            for (int i = 0; i < 3; i++) {
                #pragma unroll
                for (int j = 0; j < 3; j++) {
                    float xr[7];
                    #pragma unroll
                    for (int m = 0; m < 7; m++)
                        xr[m] = sin_[cc*((RT+2)*(WW+2)) + i*(WW+2) + j + soff[m]];
                    const float* wp = &sw[(cc*9 + i*3 + j)*OT + og*8];
                    float4 wa = *(const float4*)(wp);
                    float4 wb = *(const float4*)(wp + 4);
                    float wr[8] = {wa.x, wa.y, wa.z, wa.w, wb.x, wb.y, wb.z, wb.w};
                    #pragma unroll
                    for (int oo = 0; oo < 8; oo++)
                        #pragma unroll
                        for (int m = 0; m < 7; m++)
                            acc[oo][m] = fmaf(wr[oo], xr[m], acc[oo][m]);
                }
            }
        }
    }

    #pragma unroll
    for (int oo = 0; oo < 8; oo++) {
        int o = obase + og*8 + oo;
        #pragma unroll
        for (int m = 0; m < 7; m++) {
            int r = row0 + rowl[m];
            out[(((size_t)b*OUTC + o)*HH + r)*WW + coll[m]] = acc[oo][m];
        }
    }
}

// ---------------------------------------------------------------- launch
extern "C" void kernel_launch(void* const* d_in, const int* in_sizes, int n_in,
                              void* d_out, int out_size) {
    const float* x     = (const float*)d_in[0];
    const float* bank  = (const float*)d_in[1];
    const float* fc1_w = (const float*)d_in[2];
    const float* fc1_b = (const float*)d_in[3];
    const float* fc2_w = (const float*)d_in[4];
    const float* fc2_b = (const float*)d_in[5];
    float* out = (float*)d_out;

    pool_kernel <<<BB*CC, 256>>>(x);
    attn_kernel <<<BB, HIDN>>>(fc1_w, fc1_b, fc2_w, fc2_b);
    synth_kernel<<<(CC*9*OUTC)/256, 256>>>(bank);
    dim3 g(HH/RT, OUTC/OT, BB);   // 14 x 4 x 32
    conv_kernel <<<g, 256>>>(x, out);
}

// round 4
// speedup vs baseline: 4.3391x; 4.3391x over previous
#include <cuda_runtime.h>
#include <cuda_fp16.h>
#include <cstdint>

#define BB   32
#define CC   128
#define HH   56
#define WW   56
#define OUTC 256
#define KK   4
#define HIDN 64
#define HW   (HH*WW)

#define NK     36          // K chunks (1152 / 32)
#define AS_B   80          // A smem row stride bytes (32 halves + 8 pad)
#define BS_B   240         // B smem row stride bytes (112 halves + 8 pad)
#define A_STAGE (128*AS_B) // 10240
#define B_STAGE (32*BS_B)  // 7680
#define STAGE   (A_STAGE + B_STAGE)   // 17920

// scratch
__device__ float  g_pooled[BB*CC];
__device__ float  g_attn[BB*KK];
__device__ __half g_wh[(size_t)BB*OUTC*1152];   // [b][o][ij*128+c], fp16

// ---------------------------------------------------------------- helpers
__device__ __forceinline__ uint32_t smem_u32(const void* p) {
    uint32_t a;
    asm("{ .reg .u64 t; cvta.to.shared.u64 t, %1; cvt.u32.u64 %0, t; }" : "=r"(a) : "l"(p));
    return a;
}
__device__ __forceinline__ void ldsm_x4(uint32_t& r0, uint32_t& r1, uint32_t& r2, uint32_t& r3,
                                        uint32_t addr) {
    asm volatile("ldmatrix.sync.aligned.m8n8.x4.shared.b16 {%0,%1,%2,%3}, [%4];"
                 : "=r"(r0), "=r"(r1), "=r"(r2), "=r"(r3) : "r"(addr));
}
__device__ __forceinline__ void ldsm_x2t(uint32_t& r0, uint32_t& r1, uint32_t addr) {
    asm volatile("ldmatrix.sync.aligned.m8n8.x2.trans.shared.b16 {%0,%1}, [%2];"
                 : "=r"(r0), "=r"(r1) : "r"(addr));
}
__device__ __forceinline__ void mma16816(float* d, const uint32_t* a, const uint32_t* b) {
    asm volatile("mma.sync.aligned.m16n8k16.row.col.f32.f16.f16.f32 "
                 "{%0,%1,%2,%3}, {%4,%5,%6,%7}, {%8,%9}, {%0,%1,%2,%3};"
                 : "+f"(d[0]), "+f"(d[1]), "+f"(d[2]), "+f"(d[3])
                 : "r"(a[0]), "r"(a[1]), "r"(a[2]), "r"(a[3]), "r"(b[0]), "r"(b[1]));
}

// ---------------------------------------------------------------- pool
__global__ void pool_kernel(const float* __restrict__ x) {
    int bc = blockIdx.x;
    const float4* p = (const float4*)(x + (size_t)bc * HW);
    float s = 0.f;
    for (int i = threadIdx.x; i < HW/4; i += blockDim.x) {
        float4 v = p[i];
        s += v.x + v.y + v.z + v.w;
    }
    #pragma unroll
    for (int o = 16; o; o >>= 1) s += __shfl_down_sync(0xffffffff, s, o);
    __shared__ float ws[8];
    int lane = threadIdx.x & 31, wid = threadIdx.x >> 5;
    if (lane == 0) ws[wid] = s;
    __syncthreads();
    if (threadIdx.x == 0) {
        float t = 0.f;
        #pragma unroll
        for (int i = 0; i < 8; i++) t += ws[i];
        g_pooled[bc] = t * (1.0f / (float)HW);
    }
}

// ---------------------------------------------------------------- attn
__global__ void attn_kernel(const float* __restrict__ fc1_w, const float* __restrict__ fc1_b,
                            const float* __restrict__ fc2_w, const float* __restrict__ fc2_b) {
    int b = blockIdx.x;
    __shared__ float sp[CC];
    __shared__ float hdn[HIDN];
    int t = threadIdx.x;
    for (int i = t; i < CC; i += HIDN) sp[i] = g_pooled[b*CC + i];
    __syncthreads();
    float a = fc1_b[t];
    #pragma unroll 8
    for (int c = 0; c < CC; c++) a += sp[c] * fc1_w[t*CC + c];
    hdn[t] = fmaxf(a, 0.f);
    __syncthreads();
    if (t == 0) {
        float lg[KK];
        float mx = -1e30f;
        #pragma unroll
        for (int k = 0; k < KK; k++) {
            float s = fc2_b[k];
            for (int h = 0; h < HIDN; h++) s += hdn[h] * fc2_w[k*HIDN + h];
            lg[k] = s; mx = fmaxf(mx, s);
        }
        float den = 0.f;
        #pragma unroll
        for (int k = 0; k < KK; k++) { lg[k] = expf(lg[k] - mx); den += lg[k]; }
        float inv = 1.0f / den;
        #pragma unroll
        for (int k = 0; k < KK; k++) g_attn[b*KK + k] = lg[k] * inv;
    }
}

// ---------------------------------------------------------------- weight synthesis (fp16 out)
// g_wh[b][o][ij*128+c] = (half) sum_k attn[b][k] * bank[k][o][c*9+ij]
__global__ void synth_kernel(const float* __restrict__ bank) {
    __shared__ float sat[BB*KK];
    if (threadIdx.x < BB*KK) sat[threadIdx.x] = g_attn[threadIdx.x];
    __syncthreads();
    int idx = blockIdx.x * blockDim.x + threadIdx.x;   // < 294912
    int c   = idx & 127;
    int oij = idx >> 7;
    int ij  = oij % 9;
    int o   = oij / 9;
    float bv[KK];
    #pragma unroll
    for (int k = 0; k < KK; k++)
        bv[k] = __ldg(&bank[((size_t)k*OUTC + o) * 1152 + c*9 + ij]);
    size_t dst = (size_t)o*1152 + ij*128 + c;
    #pragma unroll 4
    for (int b = 0; b < BB; b++) {
        float w = 0.f;
        #pragma unroll
        for (int k = 0; k < KK; k++) w += sat[b*KK + k] * bv[k];
        g_wh[(size_t)b * (OUTC*1152) + dst] = __float2half_rn(w);
    }
}

// ---------------------------------------------------------------- fp16 mma.sync conv
// CTA: b = z, mtile = y (128 o), ntile = x (112 pos = 2 rows). 256 threads = 8 warps (4m x 2n).
__global__ void __launch_bounds__(256)
conv_mma_kernel(const float* __restrict__ x, float* __restrict__ out) {
    __shared__ __align__(16) char smem[2*STAGE];

    int tid  = threadIdx.x;
    int wid  = tid >> 5;
    int lane = tid & 31;
    int wm   = wid >> 1;          // 0..3 -> m base wm*32
    int wn   = wid & 1;           // 0..1 -> n base wn*56
    int b    = blockIdx.z;
    int bm   = blockIdx.y;        // 0..1
    int nt   = blockIdx.x;        // 0..27
    int r0   = nt * 2;

    uint32_t sbase = smem_u32(smem);

    const __half* wg = g_wh + ((size_t)b * OUTC + bm*128) * 1152;
    const float*  xb = x + (size_t)b * CC * HW;

    float acc[2][7][4];
    #pragma unroll
    for (int i = 0; i < 2; i++)
        #pragma unroll
        for (int j = 0; j < 7; j++)
            #pragma unroll
            for (int q = 0; q < 4; q++) acc[i][j][q] = 0.f;

    // per-thread fill coords
    int arow = tid >> 2, aq = tid & 3;                 // A: 2 iters cover 128 rows
    int bc_  = tid / 56, bpp = (tid % 56) * 2;         // B: 7 iters, pairs
    // B pair -> (pr, pc) within 2-row group, per iter c advances by 256/56... recompute per iter

    uint4 pa[2];
    float bf[14];

    auto ldg_chunk = [&](int ck) {
        int ij = ck >> 2;
        int c0 = (ck & 3) << 5;
        int di = ij / 3 - 1, dj = ij % 3 - 1;
        int koff = ij*128 + c0;
        #pragma unroll
        for (int it = 0; it < 2; it++) {
            int row = arow + it*64;
            pa[it] = *(const uint4*)(wg + (size_t)row*1152 + koff + aq*8);
        }
        #pragma unroll
        for (int it = 0; it < 7; it++) {
            int i  = tid + it*256;
            int c  = i / 56;
            int pp = (i % 56) * 2;
            int pr = pp / 56, pc = pp % 56;
            int r  = r0 + pr + di;
            int c1 = pc + dj;
            bool rok = (r >= 0) & (r < HH);
            const float* src = xb + (size_t)(c0 + c)*HW + r*WW;
            bf[2*it]   = (rok && c1 >= 0  && c1 < WW)     ? __ldg(src + c1)     : 0.f;
            bf[2*it+1] = (rok && c1+1 >= 0 && c1+1 < WW)  ? __ldg(src + c1 + 1) : 0.f;
        }
    };
    auto sts_chunk = [&](int s) {
        uint32_t ab = sbase + s*STAGE;
        uint32_t bb = ab + A_STAGE;
        #pragma unroll
        for (int it = 0; it < 2; it++) {
            int row = arow + it*64;
            *(uint4*)(smem + (ab - sbase) + row*AS_B + aq*16) = pa[it];
        }
        #pragma unroll
        for (int it = 0; it < 7; it++) {
            int i  = tid + it*256;
            int c  = i / 56;
            int pp = (i % 56) * 2;
            __half2 h = __floats2half2_rn(bf[2*it], bf[2*it+1]);
            *(__half2*)(smem + (bb - sbase) + c*BS_B + pp*2) = h;
        }
    };

    ldg_chunk(0);
    sts_chunk(0);
    __syncthreads();

    for (int ck = 0; ck < NK; ck++) {
        int s = ck & 1;
        if (ck + 1 < NK) ldg_chunk(ck + 1);

        uint32_t ab = sbase + s*STAGE;
        uint32_t bb = ab + A_STAGE;
        #pragma unroll
        for (int ks = 0; ks < 2; ks++) {
            uint32_t afrag[2][4], bfrag[7][2];
            #pragma unroll
            for (int mt = 0; mt < 2; mt++) {
                int row = wm*32 + mt*16 + (lane & 15);
                uint32_t addr = ab + row*AS_B + (lane >> 4)*16 + ks*32;
                ldsm_x4(afrag[mt][0], afrag[mt][1], afrag[mt][2], afrag[mt][3], addr);
            }
            #pragma unroll
            for (int j = 0; j < 7; j++) {
                int rowk = ks*16 + (lane & 15);
                uint32_t addr = bb + rowk*BS_B + (wn*56 + j*8)*2;
                ldsm_x2t(bfrag[j][0], bfrag[j][1], addr);
            }
            #pragma unroll
            for (int mt = 0; mt < 2; mt++)
                #pragma unroll
                for (int j = 0; j < 7; j++)
                    mma16816(acc[mt][j], afrag[mt], bfrag[j]);
        }

        if (ck + 1 < NK) sts_chunk(1 - s);
        __syncthreads();
    }

    // epilogue
    #pragma unroll
    for (int mt = 0; mt < 2; mt++) {
        int obase = bm*128 + wm*32 + mt*16 + (lane >> 2);
        #pragma unroll
        for (int half_ = 0; half_ < 2; half_++) {
            int o = obase + half_*8;
            float* dst = out + ((size_t)(b*OUTC + o))*HW + nt*112;
            #pragma unroll
            for (int j = 0; j < 7; j++) {
                int nb = wn*56 + j*8 + (lane & 3)*2;
                float2 v;
                v.x = acc[mt][j][half_*2 + 0];
                v.y = acc[mt][j][half_*2 + 1];
                *(float2*)(dst + nb) = v;
            }
        }
    }
}

// ---------------------------------------------------------------- launch
extern "C" void kernel_launch(void* const* d_in, const int* in_sizes, int n_in,
                              void* d_out, int out_size) {
    const float* x     = (const float*)d_in[0];
    const float* bank  = (const float*)d_in[1];
    const float* fc1_w = (const float*)d_in[2];
    const float* fc1_b = (const float*)d_in[3];
    const float* fc2_w = (const float*)d_in[4];
    const float* fc2_b = (const float*)d_in[5];
    float* out = (float*)d_out;

    pool_kernel <<<BB*CC, 256>>>(x);
    attn_kernel <<<BB, HIDN>>>(fc1_w, fc1_b, fc2_w, fc2_b);
    synth_kernel<<<(OUTC*1152)/256, 256>>>(bank);
    dim3 g(28, 2, BB);   // ntiles x mtiles x batch
    conv_mma_kernel<<<g, 256>>>(x, out);
}

// round 5
// speedup vs baseline: 5.5754x; 1.2849x over previous
#include <cuda_runtime.h>
#include <cuda_fp16.h>
#include <cstdint>

#define BB   32
#define CC   128
#define HH   56
#define WW   56
#define OUTC 256
#define KK   4
#define HIDN 64
#define HW   (HH*WW)

#define NK     36          // K chunks (1152 / 32)
#define AS_B   80          // A smem row stride bytes (32 halves + 8 pad)
#define BS_B   240         // B smem row stride bytes (112 halves + 8 pad)
#define A_STAGE (128*AS_B) // 10240
#define B_STAGE (32*BS_B)  // 7680
#define STAGE   (A_STAGE + B_STAGE)   // 17920

// scratch
__device__ float  g_pooled[BB*CC];
__device__ float  g_attn[BB*KK];
__device__ __half g_wh[(size_t)BB*OUTC*1152];      // [b][o][ij*128+c], fp16
__device__ __half g_xs[(size_t)3*BB*CC*HW];        // [dj+1][b][c][h][w], col-shifted fp16

// ---------------------------------------------------------------- helpers
__device__ __forceinline__ uint32_t smem_u32(const void* p) {
    uint32_t a;
    asm("{ .reg .u64 t; cvta.to.shared.u64 t, %1; cvt.u32.u64 %0, t; }" : "=r"(a) : "l"(p));
    return a;
}
__device__ __forceinline__ void ldsm_x4(uint32_t& r0, uint32_t& r1, uint32_t& r2, uint32_t& r3,
                                        uint32_t addr) {
    asm volatile("ldmatrix.sync.aligned.m8n8.x4.shared.b16 {%0,%1,%2,%3}, [%4];"
                 : "=r"(r0), "=r"(r1), "=r"(r2), "=r"(r3) : "r"(addr));
}
__device__ __forceinline__ void ldsm_x2t(uint32_t& r0, uint32_t& r1, uint32_t addr) {
    asm volatile("ldmatrix.sync.aligned.m8n8.x2.trans.shared.b16 {%0,%1}, [%2];"
                 : "=r"(r0), "=r"(r1) : "r"(addr));
}
__device__ __forceinline__ void mma16816(float* d, const uint32_t* a, const uint32_t* b) {
    asm volatile("mma.sync.aligned.m16n8k16.row.col.f32.f16.f16.f32 "
                 "{%0,%1,%2,%3}, {%4,%5,%6,%7}, {%8,%9}, {%0,%1,%2,%3};"
                 : "+f"(d[0]), "+f"(d[1]), "+f"(d[2]), "+f"(d[3])
                 : "r"(a[0]), "r"(a[1]), "r"(a[2]), "r"(a[3]), "r"(b[0]), "r"(b[1]));
}
__device__ __forceinline__ void cp16(uint32_t dst, const void* src) {
    asm volatile("cp.async.cg.shared.global [%0], [%1], 16;" :: "r"(dst), "l"(src));
}
__device__ __forceinline__ void cp4z(uint32_t dst, const void* src, int srcsz) {
    asm volatile("cp.async.ca.shared.global [%0], [%1], 4, %2;"
                 :: "r"(dst), "l"(src), "r"(srcsz));
}
#define CP_COMMIT() asm volatile("cp.async.commit_group;" ::: "memory")
#define CP_WAIT0()  asm volatile("cp.async.wait_group 0;" ::: "memory")

// ---------------------------------------------------------------- x prep: fp16 shifts + pool
// blockIdx.x = b*CC + c. Writes g_xs[j][bc][hw] = x[bc][h][w + j - 1] (0 OOB), and g_pooled.
__global__ void xprep_kernel(const float* __restrict__ x) {
    int bc = blockIdx.x;
    const float* xp = x + (size_t)bc * HW;
    __half* d0 = g_xs + ((size_t)0*BB*CC + bc)*HW;
    __half* d1 = g_xs + ((size_t)1*BB*CC + bc)*HW;
    __half* d2 = g_xs + ((size_t)2*BB*CC + bc)*HW;
    int tid = threadIdx.x;
    float s = 0.f;
    #pragma unroll
    for (int it = 0; it < 7; it++) {
        int ip = tid + it*256;              // pair index
        if (ip < HW/2) {
            int idx = ip*2;
            int w = idx % 56;
            float v0 = xp[idx], v1 = xp[idx+1];
            s += v0 + v1;
            float vm = (w > 0)  ? xp[idx-1] : 0.f;
            float vp = (w < 54) ? xp[idx+2] : 0.f;
            *(__half2*)(d0 + idx) = __floats2half2_rn(vm, v0);
            *(__half2*)(d1 + idx) = __floats2half2_rn(v0, v1);
            *(__half2*)(d2 + idx) = __floats2half2_rn(v1, vp);
        }
    }
    #pragma unroll
    for (int o = 16; o; o >>= 1) s += __shfl_down_sync(0xffffffff, s, o);
    __shared__ float ws[8];
    int lane = tid & 31, wid = tid >> 5;
    if (lane == 0) ws[wid] = s;
    __syncthreads();
    if (tid == 0) {
        float t = 0.f;
        #pragma unroll
        for (int i = 0; i < 8; i++) t += ws[i];
        g_pooled[bc] = t * (1.0f / (float)HW);
    }
}

// ---------------------------------------------------------------- attn
__global__ void attn_kernel(const float* __restrict__ fc1_w, const float* __restrict__ fc1_b,
                            const float* __restrict__ fc2_w, const float* __restrict__ fc2_b) {
    int b = blockIdx.x;
    __shared__ float sp[CC];
    __shared__ float hdn[HIDN];
    int t = threadIdx.x;
    for (int i = t; i < CC; i += HIDN) sp[i] = g_pooled[b*CC + i];
    __syncthreads();
    float a = fc1_b[t];
    #pragma unroll 8
    for (int c = 0; c < CC; c++) a += sp[c] * fc1_w[t*CC + c];
    hdn[t] = fmaxf(a, 0.f);
    __syncthreads();
    if (t == 0) {
        float lg[KK];
        float mx = -1e30f;
        #pragma unroll
        for (int k = 0; k < KK; k++) {
            float s = fc2_b[k];
            for (int h = 0; h < HIDN; h++) s += hdn[h] * fc2_w[k*HIDN + h];
            lg[k] = s; mx = fmaxf(mx, s);
        }
        float den = 0.f;
        #pragma unroll
        for (int k = 0; k < KK; k++) { lg[k] = expf(lg[k] - mx); den += lg[k]; }
        float inv = 1.0f / den;
        #pragma unroll
        for (int k = 0; k < KK; k++) g_attn[b*KK + k] = lg[k] * inv;
    }
}

// ---------------------------------------------------------------- weight synthesis (fp16 out)
__global__ void synth_kernel(const float* __restrict__ bank) {
    __shared__ float sat[BB*KK];
    if (threadIdx.x < BB*KK) sat[threadIdx.x] = g_attn[threadIdx.x];
    __syncthreads();
    int idx = blockIdx.x * blockDim.x + threadIdx.x;   // < 294912
    int c   = idx & 127;
    int oij = idx >> 7;
    int ij  = oij % 9;
    int o   = oij / 9;
    float bv[KK];
    #pragma unroll
    for (int k = 0; k < KK; k++)
        bv[k] = __ldg(&bank[((size_t)k*OUTC + o) * 1152 + c*9 + ij]);
    size_t dst = (size_t)o*1152 + ij*128 + c;
    #pragma unroll 4
    for (int b = 0; b < BB; b++) {
        float w = 0.f;
        #pragma unroll
        for (int k = 0; k < KK; k++) w += sat[b*KK + k] * bv[k];
        g_wh[(size_t)b * (OUTC*1152) + dst] = __float2half_rn(w);
    }
}

// ---------------------------------------------------------------- fp16 mma.sync conv (cp.async)
// CTA: b = z, mtile = y (128 o), ntile = x (112 pos = 2 rows). 8 warps (4m x 2n).
__global__ void __launch_bounds__(256)
conv_mma_kernel(float* __restrict__ out) {
    __shared__ __align__(16) char smem[2*STAGE];

    int tid  = threadIdx.x;
    int wid  = tid >> 5;
    int lane = tid & 31;
    int wm   = wid >> 1;
    int wn   = wid & 1;
    int b    = blockIdx.z;
    int bm   = blockIdx.y;
    int nt   = blockIdx.x;
    int r0   = nt * 2;

    uint32_t sbase = smem_u32(smem);

    const __half* wg = g_wh + ((size_t)b * OUTC + bm*128) * 1152;

    float acc[2][7][4];
    #pragma unroll
    for (int i = 0; i < 2; i++)
        #pragma unroll
        for (int j = 0; j < 7; j++)
            #pragma unroll
            for (int q = 0; q < 4; q++) acc[i][j][q] = 0.f;

    // ---- hoisted per-thread loader coords ----
    int arow = tid >> 2, aq = tid & 3;
    const __half* asrc0 = wg + (size_t)arow*1152 + aq*8;
    const __half* asrc1 = asrc0 + (size_t)64*1152;
    uint32_t dA0 = (uint32_t)arow*AS_B + aq*16;
    uint32_t dA1 = dA0 + 64*AS_B;

    int      off0[7];       // half offset into g_xs slab: (b*CC+c)*HW + (r0+pr)*WW + pc
    uint32_t dst0[7];       // byte offset into B stage
    uint32_t maskall = 0;   // bit it*3 + (di+1): row valid
    #pragma unroll
    for (int it = 0; it < 7; it++) {
        int i  = tid + it*256;        // < 1792
        int c  = i / 56;
        int pp = (i % 56) * 2;        // even position in [0,112)
        int pr = pp / 56, pc = pp % 56;
        off0[it] = (b*CC + c)*HW + (r0 + pr)*WW + pc;
        dst0[it] = (uint32_t)c*BS_B + pp*2;
        #pragma unroll
        for (int d = 0; d < 3; d++) {
            int r = r0 + pr + d - 1;
            if (r >= 0 && r < HH) maskall |= 1u << (it*3 + d);
        }
    }

    auto issue_chunk = [&](int ck, int s) {
        uint32_t ab = sbase + s*STAGE;
        uint32_t bb = ab + A_STAGE;
        cp16(ab + dA0, asrc0 + ck*32);
        cp16(ab + dA1, asrc1 + ck*32);
        int ij   = ck >> 2;
        int c0   = (ck & 3) << 5;
        int dip1 = ij / 3;                 // di+1
        int j3   = ij - dip1*3;            // dj+1
        const __half* bsrc = g_xs + (size_t)j3*(BB*CC*HW)
                           + (size_t)c0*HW + (dip1 - 1)*WW;
        #pragma unroll
        for (int it = 0; it < 7; it++) {
            int ok = (int)((maskall >> (it*3 + dip1)) & 1u);
            const __half* p = ok ? (bsrc + off0[it]) : g_xs;
            cp4z(bb + dst0[it], p, ok << 2);
        }
        CP_COMMIT();
    };

    issue_chunk(0, 0);

    for (int ck = 0; ck < NK; ck++) {
        int s = ck & 1;
        CP_WAIT0();
        __syncthreads();
        if (ck + 1 < NK) issue_chunk(ck + 1, 1 - s);

        uint32_t ab = sbase + s*STAGE;
        uint32_t bb = ab + A_STAGE;
        #pragma unroll
        for (int ks = 0; ks < 2; ks++) {
            uint32_t afrag[2][4], bfrag[7][2];
            #pragma unroll
            for (int mt = 0; mt < 2; mt++) {
                int row = wm*32 + mt*16 + (lane & 15);
                uint32_t addr = ab + row*AS_B + (lane >> 4)*16 + ks*32;
                ldsm_x4(afrag[mt][0], afrag[mt][1], afrag[mt][2], afrag[mt][3], addr);
            }
            #pragma unroll
            for (int j = 0; j < 7; j++) {
                int rowk = ks*16 + (lane & 15);
                uint32_t addr = bb + rowk*BS_B + (wn*56 + j*8)*2;
                ldsm_x2t(bfrag[j][0], bfrag[j][1], addr);
            }
            #pragma unroll
            for (int mt = 0; mt < 2; mt++)
                #pragma unroll
                for (int j = 0; j < 7; j++)
                    mma16816(acc[mt][j], afrag[mt], bfrag[j]);
        }
        __syncthreads();
    }

    // epilogue
    #pragma unroll
    for (int mt = 0; mt < 2; mt++) {
        int obase = bm*128 + wm*32 + mt*16 + (lane >> 2);
        #pragma unroll
        for (int half_ = 0; half_ < 2; half_++) {
            int o = obase + half_*8;
            float* dst = out + ((size_t)(b*OUTC + o))*HW + nt*112;
            #pragma unroll
            for (int j = 0; j < 7; j++) {
                int nb = wn*56 + j*8 + (lane & 3)*2;
                float2 v;
                v.x = acc[mt][j][half_*2 + 0];
                v.y = acc[mt][j][half_*2 + 1];
                *(float2*)(dst + nb) = v;
            }
        }
    }
}

// ---------------------------------------------------------------- launch
extern "C" void kernel_launch(void* const* d_in, const int* in_sizes, int n_in,
                              void* d_out, int out_size) {
    const float* x     = (const float*)d_in[0];
    const float* bank  = (const float*)d_in[1];
    const float* fc1_w = (const float*)d_in[2];
    const float* fc1_b = (const float*)d_in[3];
    const float* fc2_w = (const float*)d_in[4];
    const float* fc2_b = (const float*)d_in[5];
    float* out = (float*)d_out;

    xprep_kernel<<<BB*CC, 256>>>(x);
    attn_kernel <<<BB, HIDN>>>(fc1_w, fc1_b, fc2_w, fc2_b);
    synth_kernel<<<(OUTC*1152)/256, 256>>>(bank);
    dim3 g(28, 2, BB);   // ntiles x mtiles x batch
    conv_mma_kernel<<<g, 256>>>(out);
}

// round 6
// speedup vs baseline: 5.5786x; 1.0006x over previous
#include <cuda_runtime.h>
#include <cuda_fp16.h>
#include <cstdint>

#define BB   32
#define CC   128
#define HH   56
#define WW   56
#define OUTC 256
#define KK   4
#define HIDN 64
#define HW   (HH*WW)

#define NK      18              // K chunks (1152 / 64)
#define SLABR   58              // padded rows per (b,c) slab (zero rows 0 and 57)
#define SLAB    (SLABR*WW)      // 3248 halves
#define AS_B    144             // A smem row stride bytes (64 halves + 16 pad)
#define BS_B    240             // B smem row stride bytes (112 halves + 16 pad)
#define A_STAGE (128*AS_B)      // 18432
#define B_STAGE (64*BS_B)       // 15360
#define STAGE   (A_STAGE + B_STAGE)   // 33792
#define SMEM_TOTAL (2*STAGE)          // 67584 (dynamic, opt-in)

// scratch
__device__ float  g_pooled[BB*CC];
__device__ float  g_attn[BB*KK];
__device__ __half g_wh[(size_t)BB*OUTC*1152];      // [b][o][ij*128+c]
__device__ __half g_xs[(size_t)3*BB*CC*SLAB];      // [dj+1][b][c][58][56], zero-padded rows

// ---------------------------------------------------------------- helpers
__device__ __forceinline__ uint32_t smem_u32(const void* p) {
    uint32_t a;
    asm("{ .reg .u64 t; cvta.to.shared.u64 t, %1; cvt.u32.u64 %0, t; }" : "=r"(a) : "l"(p));
    return a;
}
__device__ __forceinline__ void ldsm_x4(uint32_t& r0, uint32_t& r1, uint32_t& r2, uint32_t& r3,
                                        uint32_t addr) {
    asm volatile("ldmatrix.sync.aligned.m8n8.x4.shared.b16 {%0,%1,%2,%3}, [%4];"
                 : "=r"(r0), "=r"(r1), "=r"(r2), "=r"(r3) : "r"(addr));
}
__device__ __forceinline__ void ldsm_x2t(uint32_t& r0, uint32_t& r1, uint32_t addr) {
    asm volatile("ldmatrix.sync.aligned.m8n8.x2.trans.shared.b16 {%0,%1}, [%2];"
                 : "=r"(r0), "=r"(r1) : "r"(addr));
}
__device__ __forceinline__ void mma16816(float* d, const uint32_t* a, const uint32_t* b) {
    asm volatile("mma.sync.aligned.m16n8k16.row.col.f32.f16.f16.f32 "
                 "{%0,%1,%2,%3}, {%4,%5,%6,%7}, {%8,%9}, {%0,%1,%2,%3};"
                 : "+f"(d[0]), "+f"(d[1]), "+f"(d[2]), "+f"(d[3])
                 : "r"(a[0]), "r"(a[1]), "r"(a[2]), "r"(a[3]), "r"(b[0]), "r"(b[1]));
}
__device__ __forceinline__ void cp16(uint32_t dst, const void* src) {
    asm volatile("cp.async.cg.shared.global [%0], [%1], 16;" :: "r"(dst), "l"(src));
}
__device__ __forceinline__ void cp4(uint32_t dst, const void* src) {
    asm volatile("cp.async.ca.shared.global [%0], [%1], 4;" :: "r"(dst), "l"(src));
}
#define CP_COMMIT() asm volatile("cp.async.commit_group;" ::: "memory")
#define CP_WAIT0()  asm volatile("cp.async.wait_group 0;" ::: "memory")

// ---------------------------------------------------------------- x prep: fp16 shifts + pool
// blockIdx.x = b*CC + c. g_xs slab rows 1..56 = x rows 0..55 col-shifted; rows 0,57 zero.
__global__ void xprep_kernel(const float* __restrict__ x) {
    int bc = blockIdx.x;
    const float* xp = x + (size_t)bc * HW;
    __half* d0 = g_xs + ((size_t)0*BB*CC + bc)*SLAB;
    __half* d1 = g_xs + ((size_t)1*BB*CC + bc)*SLAB;
    __half* d2 = g_xs + ((size_t)2*BB*CC + bc)*SLAB;
    int tid = threadIdx.x;
    // zero pad rows (56 pairs per row edge per slab)
    if (tid < 56) {
        __half2 z = __floats2half2_rn(0.f, 0.f);
        *(__half2*)(d0 + tid*2) = z;  *(__half2*)(d0 + 57*WW + tid*2) = z;
        *(__half2*)(d1 + tid*2) = z;  *(__half2*)(d1 + 57*WW + tid*2) = z;
        *(__half2*)(d2 + tid*2) = z;  *(__half2*)(d2 + 57*WW + tid*2) = z;
    }
    float s = 0.f;
    #pragma unroll
    for (int it = 0; it < 7; it++) {
        int ip = tid + it*256;              // pair index
        if (ip < HW/2) {
            int idx = ip*2;
            int w = idx % 56;
            float v0 = xp[idx], v1 = xp[idx+1];
            s += v0 + v1;
            float vm = (w > 0)  ? xp[idx-1] : 0.f;
            float vp = (w < 54) ? xp[idx+2] : 0.f;
            *(__half2*)(d0 + WW + idx) = __floats2half2_rn(vm, v0);
            *(__half2*)(d1 + WW + idx) = __floats2half2_rn(v0, v1);
            *(__half2*)(d2 + WW + idx) = __floats2half2_rn(v1, vp);
        }
    }
    #pragma unroll
    for (int o = 16; o; o >>= 1) s += __shfl_down_sync(0xffffffff, s, o);
    __shared__ float ws[8];
    int lane = tid & 31, wid = tid >> 5;
    if (lane == 0) ws[wid] = s;
    __syncthreads();
    if (tid == 0) {
        float t = 0.f;
        #pragma unroll
        for (int i = 0; i < 8; i++) t += ws[i];
        g_pooled[bc] = t * (1.0f / (float)HW);
    }
}

// ---------------------------------------------------------------- attn
__global__ void attn_kernel(const float* __restrict__ fc1_w, const float* __restrict__ fc1_b,
                            const float* __restrict__ fc2_w, const float* __restrict__ fc2_b) {
    int b = blockIdx.x;
    __shared__ float sp[CC];
    __shared__ float hdn[HIDN];
    int t = threadIdx.x;
    for (int i = t; i < CC; i += HIDN) sp[i] = g_pooled[b*CC + i];
    __syncthreads();
    float a = fc1_b[t];
    #pragma unroll 8
    for (int c = 0; c < CC; c++) a += sp[c] * fc1_w[t*CC + c];
    hdn[t] = fmaxf(a, 0.f);
    __syncthreads();
    if (t == 0) {
        float lg[KK];
        float mx = -1e30f;
        #pragma unroll
        for (int k = 0; k < KK; k++) {
            float s = fc2_b[k];
            for (int h = 0; h < HIDN; h++) s += hdn[h] * fc2_w[k*HIDN + h];
            lg[k] = s; mx = fmaxf(mx, s);
        }
        float den = 0.f;
        #pragma unroll
        for (int k = 0; k < KK; k++) { lg[k] = expf(lg[k] - mx); den += lg[k]; }
        float inv = 1.0f / den;
        #pragma unroll
        for (int k = 0; k < KK; k++) g_attn[b*KK + k] = lg[k] * inv;
    }
}

// ---------------------------------------------------------------- weight synthesis (fp16 out)
__global__ void synth_kernel(const float* __restrict__ bank) {
    __shared__ float sat[BB*KK];
    if (threadIdx.x < BB*KK) sat[threadIdx.x] = g_attn[threadIdx.x];
    __syncthreads();
    int idx = blockIdx.x * blockDim.x + threadIdx.x;   // < 294912
    int c   = idx & 127;
    int oij = idx >> 7;
    int ij  = oij % 9;
    int o   = oij / 9;
    float bv[KK];
    #pragma unroll
    for (int k = 0; k < KK; k++)
        bv[k] = __ldg(&bank[((size_t)k*OUTC + o) * 1152 + c*9 + ij]);
    size_t dst = (size_t)o*1152 + ij*128 + c;
    #pragma unroll 4
    for (int b = 0; b < BB; b++) {
        float w = 0.f;
        #pragma unroll
        for (int k = 0; k < KK; k++) w += sat[b*KK + k] * bv[k];
        g_wh[(size_t)b * (OUTC*1152) + dst] = __float2half_rn(w);
    }
}

// ---------------------------------------------------------------- fp16 mma.sync conv
// CTA: b = z, mtile = y (128 o), ntile = x (112 pos = 2 rows). 8 warps (4m x 2n). K chunk 64.
__global__ void __launch_bounds__(256, 2)
conv_mma_kernel(float* __restrict__ out) {
    extern __shared__ __align__(16) char smem[];

    int tid  = threadIdx.x;
    int wid  = tid >> 5;
    int lane = tid & 31;
    int wm   = wid >> 1;
    int wn   = wid & 1;
    int b    = blockIdx.z;
    int bm   = blockIdx.y;
    int nt   = blockIdx.x;
    int r0   = nt * 2;

    uint32_t sbase = smem_u32(smem);

    const __half* wg = g_wh + ((size_t)b * OUTC + bm*128) * 1152;

    float acc[2][7][4];
    #pragma unroll
    for (int i = 0; i < 2; i++)
        #pragma unroll
        for (int j = 0; j < 7; j++)
            #pragma unroll
            for (int q = 0; q < 4; q++) acc[i][j][q] = 0.f;

    // ---- fully uniform loader bases ----
    // A: thread -> row = tid>>3 (+32/it), q = tid&7. 4 cp16/chunk.
    const __half* asrc = wg + (size_t)(tid >> 3)*1152 + (tid & 7)*8;
    uint32_t dA = (uint32_t)(tid >> 3)*AS_B + (tid & 7)*16;
    // B: thread -> channel c = tid>>2, pp = 2*(tid&3) + 8*it. 14 cp4/chunk, +16B stride.
    const __half* bsrc = g_xs + (size_t)(b*CC + (tid >> 2))*SLAB
                       + (1 + r0)*WW + 2*(tid & 3);
    uint32_t dB = (uint32_t)(tid >> 2)*BS_B + (tid & 3)*4;

    auto issue_chunk = [&](int ck, int s) {
        uint32_t ab = sbase + s*STAGE;
        uint32_t bb = ab + A_STAGE;
        int ij   = ck >> 1;
        int c0   = (ck & 1) << 6;
        int koff = ij*128 + c0;
        const __half* ap = asrc + koff;
        #pragma unroll
        for (int it = 0; it < 4; it++)
            cp16(ab + dA + it*(32*AS_B), ap + it*(32*1152));
        int dip1 = ij / 3;                 // di+1
        int j3   = ij - dip1*3;            // dj+1
        const __half* bp = bsrc + (size_t)j3*(BB*CC*SLAB)
                         + (size_t)c0*SLAB + (dip1 - 1)*WW;
        uint32_t bd = bb + dB;
        #pragma unroll
        for (int it = 0; it < 14; it++)
            cp4(bd + it*16, bp + it*8);
        CP_COMMIT();
    };

    issue_chunk(0, 0);

    for (int ck = 0; ck < NK; ck++) {
        int s = ck & 1;
        CP_WAIT0();
        __syncthreads();
        if (ck + 1 < NK) issue_chunk(ck + 1, 1 - s);

        uint32_t ab = sbase + s*STAGE;
        uint32_t bb = ab + A_STAGE;
        #pragma unroll
        for (int ks = 0; ks < 4; ks++) {
            uint32_t afrag[2][4], bfrag[7][2];
            #pragma unroll
            for (int mt = 0; mt < 2; mt++) {
                int row = wm*32 + mt*16 + (lane & 15);
                uint32_t addr = ab + row*AS_B + (lane >> 4)*16 + ks*32;
                ldsm_x4(afrag[mt][0], afrag[mt][1], afrag[mt][2], afrag[mt][3], addr);
            }
            #pragma unroll
            for (int j = 0; j < 7; j++) {
                int rowk = ks*16 + (lane & 15);
                uint32_t addr = bb + rowk*BS_B + (wn*56 + j*8)*2;
                ldsm_x2t(bfrag[j][0], bfrag[j][1], addr);
            }
            #pragma unroll
            for (int mt = 0; mt < 2; mt++)
                #pragma unroll
                for (int j = 0; j < 7; j++)
                    mma16816(acc[mt][j], afrag[mt], bfrag[j]);
        }
    }

    // epilogue
    #pragma unroll
    for (int mt = 0; mt < 2; mt++) {
        int obase = bm*128 + wm*32 + mt*16 + (lane >> 2);
        #pragma unroll
        for (int half_ = 0; half_ < 2; half_++) {
            int o = obase + half_*8;
            float* dst = out + ((size_t)(b*OUTC + o))*HW + nt*112;
            #pragma unroll
            for (int j = 0; j < 7; j++) {
                int nb = wn*56 + j*8 + (lane & 3)*2;
                float2 v;
                v.x = acc[mt][j][half_*2 + 0];
                v.y = acc[mt][j][half_*2 + 1];
                *(float2*)(dst + nb) = v;
            }
        }
    }
}

// ---------------------------------------------------------------- launch
extern "C" void kernel_launch(void* const* d_in, const int* in_sizes, int n_in,
                              void* d_out, int out_size) {
    const float* x     = (const float*)d_in[0];
    const float* bank  = (const float*)d_in[1];
    const float* fc1_w = (const float*)d_in[2];
    const float* fc1_b = (const float*)d_in[3];
    const float* fc2_w = (const float*)d_in[4];
    const float* fc2_b = (const float*)d_in[5];
    float* out = (float*)d_out;

    cudaFuncSetAttribute(conv_mma_kernel,
                         cudaFuncAttributeMaxDynamicSharedMemorySize, SMEM_TOTAL);

    xprep_kernel<<<BB*CC, 256>>>(x);
    attn_kernel <<<BB, HIDN>>>(fc1_w, fc1_b, fc2_w, fc2_b);
    synth_kernel<<<(OUTC*1152)/256, 256>>>(bank);
    dim3 g(28, 2, BB);   // ntiles x mtiles x batch
    conv_mma_kernel<<<g, 256, SMEM_TOTAL>>>(out);
}

// round 7
// speedup vs baseline: 6.6562x; 1.1932x over previous
#include <cuda_runtime.h>
#include <cuda_fp16.h>
#include <cstdint>

#define BB   32
#define CC   128
#define HH   56
#define WW   56
#define OUTC 256
#define KK   4
#define HIDN 64
#define HW   (HH*WW)

#define NK      36              // K chunks (1152 / 32)
#define NSTAGE  4
#define SLABR   58              // padded rows per (b,c) slab (zero rows 0 and 57)
#define SLAB    (SLABR*WW)      // 3248 halves
#define AS_B    80              // A smem row stride bytes (32 halves + 8 pad)
#define BS_B    240             // B smem row stride bytes (112 halves + 8 pad)
#define A_STAGE (128*AS_B)      // 10240
#define B_STAGE (32*BS_B)       // 7680
#define STAGE   (A_STAGE + B_STAGE)     // 17920
#define SMEM_TOTAL (NSTAGE*STAGE)       // 71680 (dynamic, opt-in)

// scratch
__device__ float  g_pooled[BB*CC];
__device__ float  g_attn[BB*KK];
__device__ __half g_wh[(size_t)BB*OUTC*1152];      // [b][o][ij*128+c]
__device__ __half g_xs[(size_t)3*BB*CC*SLAB];      // [dj+1][b][c][58][56], zero-padded rows

// ---------------------------------------------------------------- helpers
__device__ __forceinline__ uint32_t smem_u32(const void* p) {
    uint32_t a;
    asm("{ .reg .u64 t; cvta.to.shared.u64 t, %1; cvt.u32.u64 %0, t; }" : "=r"(a) : "l"(p));
    return a;
}
__device__ __forceinline__ void ldsm_x4(uint32_t& r0, uint32_t& r1, uint32_t& r2, uint32_t& r3,
                                        uint32_t addr) {
    asm volatile("ldmatrix.sync.aligned.m8n8.x4.shared.b16 {%0,%1,%2,%3}, [%4];"
                 : "=r"(r0), "=r"(r1), "=r"(r2), "=r"(r3) : "r"(addr));
}
__device__ __forceinline__ void ldsm_x2t(uint32_t& r0, uint32_t& r1, uint32_t addr) {
    asm volatile("ldmatrix.sync.aligned.m8n8.x2.trans.shared.b16 {%0,%1}, [%2];"
                 : "=r"(r0), "=r"(r1) : "r"(addr));
}
__device__ __forceinline__ void mma16816(float* d, const uint32_t* a, const uint32_t* b) {
    asm volatile("mma.sync.aligned.m16n8k16.row.col.f32.f16.f16.f32 "
                 "{%0,%1,%2,%3}, {%4,%5,%6,%7}, {%8,%9}, {%0,%1,%2,%3};"
                 : "+f"(d[0]), "+f"(d[1]), "+f"(d[2]), "+f"(d[3])
                 : "r"(a[0]), "r"(a[1]), "r"(a[2]), "r"(a[3]), "r"(b[0]), "r"(b[1]));
}
__device__ __forceinline__ void cp16(uint32_t dst, const void* src) {
    asm volatile("cp.async.cg.shared.global [%0], [%1], 16;" :: "r"(dst), "l"(src));
}
#define CP_COMMIT() asm volatile("cp.async.commit_group;" ::: "memory")
#define CP_WAIT2()  asm volatile("cp.async.wait_group 2;" ::: "memory")
#define CP_WAIT0()  asm volatile("cp.async.wait_group 0;" ::: "memory")

// ---------------------------------------------------------------- x prep: fp16 shifts + pool
__global__ void xprep_kernel(const float* __restrict__ x) {
    int bc = blockIdx.x;
    const float* xp = x + (size_t)bc * HW;
    __half* d0 = g_xs + ((size_t)0*BB*CC + bc)*SLAB;
    __half* d1 = g_xs + ((size_t)1*BB*CC + bc)*SLAB;
    __half* d2 = g_xs + ((size_t)2*BB*CC + bc)*SLAB;
    int tid = threadIdx.x;
    if (tid < 56) {
        __half2 z = __floats2half2_rn(0.f, 0.f);
        *(__half2*)(d0 + tid*2) = z;  *(__half2*)(d0 + 57*WW + tid*2) = z;
        *(__half2*)(d1 + tid*2) = z;  *(__half2*)(d1 + 57*WW + tid*2) = z;
        *(__half2*)(d2 + tid*2) = z;  *(__half2*)(d2 + 57*WW + tid*2) = z;
    }
    float s = 0.f;
    #pragma unroll
    for (int it = 0; it < 7; it++) {
        int ip = tid + it*256;
        if (ip < HW/2) {
            int idx = ip*2;
            int w = idx % 56;
            float v0 = xp[idx], v1 = xp[idx+1];
            s += v0 + v1;
            float vm = (w > 0)  ? xp[idx-1] : 0.f;
            float vp = (w < 54) ? xp[idx+2] : 0.f;
            *(__half2*)(d0 + WW + idx) = __floats2half2_rn(vm, v0);
            *(__half2*)(d1 + WW + idx) = __floats2half2_rn(v0, v1);
            *(__half2*)(d2 + WW + idx) = __floats2half2_rn(v1, vp);
        }
    }
    #pragma unroll
    for (int o = 16; o; o >>= 1) s += __shfl_down_sync(0xffffffff, s, o);
    __shared__ float ws[8];
    int lane = tid & 31, wid = tid >> 5;
    if (lane == 0) ws[wid] = s;
    __syncthreads();
    if (tid == 0) {
        float t = 0.f;
        #pragma unroll
        for (int i = 0; i < 8; i++) t += ws[i];
        g_pooled[bc] = t * (1.0f / (float)HW);
    }
}

// ---------------------------------------------------------------- attn
__global__ void attn_kernel(const float* __restrict__ fc1_w, const float* __restrict__ fc1_b,
                            const float* __restrict__ fc2_w, const float* __restrict__ fc2_b) {
    int b = blockIdx.x;
    __shared__ float sp[CC];
    __shared__ float hdn[HIDN];
    int t = threadIdx.x;
    for (int i = t; i < CC; i += HIDN) sp[i] = g_pooled[b*CC + i];
    __syncthreads();
    float a = fc1_b[t];
    #pragma unroll 8
    for (int c = 0; c < CC; c++) a += sp[c] * fc1_w[t*CC + c];
    hdn[t] = fmaxf(a, 0.f);
    __syncthreads();
    if (t == 0) {
        float lg[KK];
        float mx = -1e30f;
        #pragma unroll
        for (int k = 0; k < KK; k++) {
            float s = fc2_b[k];
            for (int h = 0; h < HIDN; h++) s += hdn[h] * fc2_w[k*HIDN + h];
            lg[k] = s; mx = fmaxf(mx, s);
        }
        float den = 0.f;
        #pragma unroll
        for (int k = 0; k < KK; k++) { lg[k] = expf(lg[k] - mx); den += lg[k]; }
        float inv = 1.0f / den;
        #pragma unroll
        for (int k = 0; k < KK; k++) g_attn[b*KK + k] = lg[k] * inv;
    }
}

// ---------------------------------------------------------------- weight synthesis (fp16 out)
__global__ void synth_kernel(const float* __restrict__ bank) {
    __shared__ float sat[BB*KK];
    if (threadIdx.x < BB*KK) sat[threadIdx.x] = g_attn[threadIdx.x];
    __syncthreads();
    int idx = blockIdx.x * blockDim.x + threadIdx.x;
    int c   = idx & 127;
    int oij = idx >> 7;
    int ij  = oij % 9;
    int o   = oij / 9;
    float bv[KK];
    #pragma unroll
    for (int k = 0; k < KK; k++)
        bv[k] = __ldg(&bank[((size_t)k*OUTC + o) * 1152 + c*9 + ij]);
    size_t dst = (size_t)o*1152 + ij*128 + c;
    #pragma unroll 4
    for (int b = 0; b < BB; b++) {
        float w = 0.f;
        #pragma unroll
        for (int k = 0; k < KK; k++) w += sat[b*KK + k] * bv[k];
        g_wh[(size_t)b * (OUTC*1152) + dst] = __float2half_rn(w);
    }
}

// ---------------------------------------------------------------- fp16 mma.sync conv
// CTA: b=z, mtile=y (128 o), ntile=x (112 pos = 2 rows). 8 warps (4m x 2n).
// K=32 chunks, 4-stage cp.async ring, all fills 16B.
__global__ void __launch_bounds__(256, 2)
conv_mma_kernel(float* __restrict__ out) {
    extern __shared__ __align__(16) char smem[];

    int tid  = threadIdx.x;
    int wid  = tid >> 5;
    int lane = tid & 31;
    int wm   = wid >> 1;
    int wn   = wid & 1;
    int b    = blockIdx.z;
    int bm   = blockIdx.y;
    int nt   = blockIdx.x;
    int r0   = nt * 2;

    uint32_t sbase = smem_u32(smem);

    const __half* wg = g_wh + ((size_t)b * OUTC + bm*128) * 1152;

    float acc[2][7][4];
    #pragma unroll
    for (int i = 0; i < 2; i++)
        #pragma unroll
        for (int j = 0; j < 7; j++)
            #pragma unroll
            for (int q = 0; q < 4; q++) acc[i][j][q] = 0.f;

    // ---- A loader: 512 cp16/chunk. idx = tid + it*256, row = idx>>2, q = idx&3.
    int ar = tid >> 2, aq = tid & 3;
    const __half* asrc = wg + (size_t)ar*1152 + aq*8;    // + ck*32 per chunk
    uint32_t dA = (uint32_t)ar*AS_B + aq*16;
    // ---- B loader: 448 cp16/chunk, contiguous 224B per channel.
    // idx = tid (+256), c = idx/14, q = idx%14. src halves: c*SLAB + q*8. dst: c*BS_B + q*16.
    int bi0 = tid, bi1 = tid + 256;
    int bc0 = bi0 / 14, bq0 = bi0 % 14;
    int bc1 = bi1 / 14, bq1 = bi1 % 14;
    bool bhas1 = bi1 < 448;
    size_t bs0 = (size_t)bc0*SLAB + bq0*8;
    size_t bs1 = (size_t)bc1*SLAB + bq1*8;
    uint32_t dB0 = (uint32_t)bc0*BS_B + bq0*16;
    uint32_t dB1 = (uint32_t)bc1*BS_B + bq1*16;

    auto issue_chunk = [&](int ck) {
        uint32_t ab = sbase + (ck & (NSTAGE-1))*STAGE;
        uint32_t bb = ab + A_STAGE;
        const __half* ap = asrc + ck*32;
        cp16(ab + dA, ap);
        cp16(ab + dA + 64*AS_B, ap + (size_t)64*1152);
        int ij   = ck >> 2;              // 0..8
        int c0   = (ck & 3) << 5;        // 0,32,64,96
        int dip1 = ij / 3;
        int j3   = ij - dip1*3;
        const __half* bp = g_xs + ((size_t)j3*BB*CC + b*CC + c0)*SLAB
                         + (size_t)(r0 + dip1)*WW;
        cp16(bb + dB0, bp + bs0);
        if (bhas1) cp16(bb + dB1, bp + bs1);
        CP_COMMIT();
    };

    issue_chunk(0);
    issue_chunk(1);
    issue_chunk(2);

    for (int ck = 0; ck < NK; ck++) {
        CP_WAIT2();
        __syncthreads();
        if (ck + 3 < NK) issue_chunk(ck + 3);

        uint32_t ab = sbase + (ck & (NSTAGE-1))*STAGE;
        uint32_t bb = ab + A_STAGE;
        #pragma unroll
        for (int ks = 0; ks < 2; ks++) {
            uint32_t afrag[2][4], bfrag[7][2];
            #pragma unroll
            for (int mt = 0; mt < 2; mt++) {
                int row = wm*32 + mt*16 + (lane & 15);
                uint32_t addr = ab + row*AS_B + (lane >> 4)*16 + ks*32;
                ldsm_x4(afrag[mt][0], afrag[mt][1], afrag[mt][2], afrag[mt][3], addr);
            }
            #pragma unroll
            for (int j = 0; j < 7; j++) {
                int rowk = ks*16 + (lane & 15);
                uint32_t addr = bb + rowk*BS_B + (wn*56 + j*8)*2;
                ldsm_x2t(bfrag[j][0], bfrag[j][1], addr);
            }
            #pragma unroll
            for (int mt = 0; mt < 2; mt++)
                #pragma unroll
                for (int j = 0; j < 7; j++)
                    mma16816(acc[mt][j], afrag[mt], bfrag[j]);
        }
    }
    CP_WAIT0();

    // epilogue
    #pragma unroll
    for (int mt = 0; mt < 2; mt++) {
        int obase = bm*128 + wm*32 + mt*16 + (lane >> 2);
        #pragma unroll
        for (int half_ = 0; half_ < 2; half_++) {
            int o = obase + half_*8;
            float* dst = out + ((size_t)(b*OUTC + o))*HW + nt*112;
            #pragma unroll
            for (int j = 0; j < 7; j++) {
                int nb = wn*56 + j*8 + (lane & 3)*2;
                float2 v;
                v.x = acc[mt][j][half_*2 + 0];
                v.y = acc[mt][j][half_*2 + 1];
                *(float2*)(dst + nb) = v;
            }
        }
    }
}

// ---------------------------------------------------------------- launch
extern "C" void kernel_launch(void* const* d_in, const int* in_sizes, int n_in,
                              void* d_out, int out_size) {
    const float* x     = (const float*)d_in[0];
    const float* bank  = (const float*)d_in[1];
    const float* fc1_w = (const float*)d_in[2];
    const float* fc1_b = (const float*)d_in[3];
    const float* fc2_w = (const float*)d_in[4];
    const float* fc2_b = (const float*)d_in[5];
    float* out = (float*)d_out;

    cudaFuncSetAttribute(conv_mma_kernel,
                         cudaFuncAttributeMaxDynamicSharedMemorySize, SMEM_TOTAL);

    xprep_kernel<<<BB*CC, 256>>>(x);
    attn_kernel <<<BB, HIDN>>>(fc1_w, fc1_b, fc2_w, fc2_b);
    synth_kernel<<<(OUTC*1152)/256, 256>>>(bank);
    dim3 g(28, 2, BB);   // ntiles x mtiles x batch
    conv_mma_kernel<<<g, 256, SMEM_TOTAL>>>(out);
}